// round 11
// baseline (speedup 1.0000x reference)
#include <cuda_runtime.h>

// SpatialLoss on GB300 (sm_103a) — single fused kernel.
//
// Math: conv is linear =>
//   d = grad_conv(avgpool4(mean_c(x - pred)))  (p = pooled channel-mean diff)
// Pair identity (each interior pair counted by both endpoint pixels):
//   E = 2*sum_{horiz pairs}(p_j - p_{j+1})^2 + 2*sum_{vert pairs}(p_i - p_{i+1})^2
//     + sum_{left/right edge} p^2 + sum_{top/bottom edge} p^2
// loss = E / (B*128*128)
//
// Decomposition: block = 32-pooled-row x 128-col band of one image
// (32 images x 4 bands = 128 blocks, one wave on 148 SMs). Each block:
//   1. streams its 4*32 input rows (+ one recomputed halo row for the
//      band-crossing vertical pair, ~3% redundant reads) -> smem pooled tile
//   2. pair-stencil on smem, block reduce, one atomicAdd.

#define BB 32
#define CC 3
#define HH 512
#define W4 (512 / 4)          // row length in float4
#define PH 128
#define PW 128
#define BAND 32               // pooled rows per block
#define NPIX (BB * PH * PW)   // 524288

__global__ void __launch_bounds__(256) fused_spatial_loss_kernel(
    const float* __restrict__ x, const float* __restrict__ pred,
    float* __restrict__ out)
{
    __shared__ float sp[(BAND + 1) * PW];   // band + halo row (16.5 KB)

    const int b    = blockIdx.x >> 2;
    const int band = blockIdx.x & 3;
    const int r0   = band * BAND;

    const int nrows = (band < 3) ? (BAND + 1) : BAND;  // halo row unless last band
    const int npx   = nrows * PW;

    const float4* __restrict__ x4 = (const float4*)x;
    const float4* __restrict__ p4 = (const float4*)pred;

    // ---- Phase 1: pooled channel-mean diff into smem (streaming, HBM-bound)
    for (int pix = threadIdx.x; pix < npx; pix += 256) {
        const int j  = pix & (PW - 1);
        const int il = pix >> 7;
        const int i  = r0 + il;           // global pooled row (halo: i = r0+32)

        float s = 0.0f;
#pragma unroll
        for (int c = 0; c < CC; c++) {
#pragma unroll
            for (int dh = 0; dh < 4; dh++) {
                const int off = ((b * CC + c) * HH + (4 * i + dh)) * W4 + j;
                const float4 a = __ldcs(&x4[off]);
                const float4 q = __ldcs(&p4[off]);
                s += (a.x - q.x) + (a.y - q.y) + (a.z - q.z) + (a.w - q.w);
            }
        }
        sp[pix] = s * (1.0f / 48.0f);
    }
    __syncthreads();

    // ---- Phase 2: pair stencil over the band's 32x128 pixels (smem only)
    float acc = 0.0f;
#pragma unroll 4
    for (int pix = threadIdx.x; pix < BAND * PW; pix += 256) {  // 16 iters exact
        const int j  = pix & (PW - 1);
        const int il = pix >> 7;
        const float p = sp[pix];

        // horizontal pair (j, j+1), weight 2; edges contribute p^2
        if (j < PW - 1) {
            const float d = p - sp[pix + 1];
            acc += 2.0f * d * d;
        } else {
            acc += p * p;                  // right edge
        }
        if (j == 0) acc += p * p;          // left edge

        // vertical pair (row il, il+1): in-band rows always, plus the
        // band-crossing pair via the halo row (band<3). Last row of the
        // last band is the bottom edge instead.
        if ((band < 3) || (il < BAND - 1)) {
            const float d = p - sp[pix + PW];
            acc += 2.0f * d * d;
        } else {
            acc += p * p;                  // bottom edge (global row 127)
        }
        if (band == 0 && il == 0) acc += p * p;   // top edge (global row 0)
    }

    // ---- block reduction, one atomic per block (128 total)
#pragma unroll
    for (int off = 16; off > 0; off >>= 1)
        acc += __shfl_down_sync(0xFFFFFFFFu, acc, off);

    __shared__ float warp_sums[8];
    const int lane = threadIdx.x & 31;
    const int wid  = threadIdx.x >> 5;
    if (lane == 0) warp_sums[wid] = acc;
    __syncthreads();

    if (wid == 0) {
        float s = (lane < 8) ? warp_sums[lane] : 0.0f;
#pragma unroll
        for (int off = 4; off > 0; off >>= 1)
            s += __shfl_down_sync(0xFFFFFFFFu, s, off);
        if (lane == 0)
            atomicAdd(out, s * (1.0f / (float)NPIX));
    }
}

extern "C" void kernel_launch(void* const* d_in, const int* in_sizes, int n_in,
                              void* d_out, int out_size)
{
    const float* x    = (const float*)d_in[0];
    const float* pred = (const float*)d_in[1];
    float* out = (float*)d_out;

    cudaMemsetAsync(out, 0, sizeof(float));
    fused_spatial_loss_kernel<<<BB * 4, 256>>>(x, pred, out);  // 128 blocks
}

// round 14
// speedup vs baseline: 2.4700x; 2.4700x over previous
#include <cuda_runtime.h>

// SpatialLoss on GB300 (sm_103a) — single fused kernel, high-occupancy rev.
//
// Math: conv is linear =>
//   d = grad_conv(avgpool4(mean_c(x - pred)))  (p = pooled channel-mean diff)
// Pair identity (each interior pair counted by both endpoint pixels):
//   E = 2*sum_{horiz pairs}(dp)^2 + 2*sum_{vert pairs}(dp)^2
//     + sum_{left/right edge} p^2 + sum_{top/bottom edge} p^2
// loss = E / (B*128*128)
//
// Decomposition: block = 32-pooled-row x 128-col band of one image
// (32 images x 4 bands = 128 blocks, ONE wave). 1024 threads/block
// (32 warps/SM — R10's 256-thr version stalled at occ=12.5%, DRAM=27%).
//   1. stream 4*32 input rows (+1 recomputed halo row, ~3% redundant)
//      -> smem pooled tile
//   2. pair-stencil in smem, block reduce, one atomicAdd (128 total).

#define BB 32
#define CC 3
#define HH 512
#define W4 (512 / 4)          // row length in float4
#define PH 128
#define PW 128
#define BAND 32               // pooled rows per block
#define NPIX (BB * PH * PW)   // 524288
#define NTHR 1024

__global__ void __launch_bounds__(NTHR) fused_spatial_loss_kernel(
    const float* __restrict__ x, const float* __restrict__ pred,
    float* __restrict__ out)
{
    __shared__ float sp[(BAND + 1) * PW];   // band + halo row (16.5 KB)

    const int b    = blockIdx.x >> 2;
    const int band = blockIdx.x & 3;
    const int r0   = band * BAND;

    const int nrows = (band < 3) ? (BAND + 1) : BAND;  // halo row unless last band
    const int npx   = nrows * PW;                       // 4224 or 4096

    const float4* __restrict__ x4 = (const float4*)x;
    const float4* __restrict__ p4 = (const float4*)pred;

    // ---- Phase 1: pooled channel-mean diff into smem (streaming, HBM-bound)
    for (int pix = threadIdx.x; pix < npx; pix += NTHR) {
        const int j  = pix & (PW - 1);
        const int il = pix >> 7;
        const int i  = r0 + il;           // global pooled row (halo: i = r0+32)

        float s = 0.0f;
#pragma unroll
        for (int c = 0; c < CC; c++) {
#pragma unroll
            for (int dh = 0; dh < 4; dh++) {
                const int off = ((b * CC + c) * HH + (4 * i + dh)) * W4 + j;
                const float4 a = __ldcs(&x4[off]);   // streaming, evict-first
                const float4 q = __ldcs(&p4[off]);
                s += (a.x - q.x) + (a.y - q.y) + (a.z - q.z) + (a.w - q.w);
            }
        }
        sp[pix] = s * (1.0f / 48.0f);
    }
    __syncthreads();

    // ---- Phase 2: pair stencil over the band's 32x128 pixels (smem only)
    float acc = 0.0f;
#pragma unroll
    for (int pix = threadIdx.x; pix < BAND * PW; pix += NTHR) {  // 4 iters exact
        const int j  = pix & (PW - 1);
        const int il = pix >> 7;
        const float p = sp[pix];

        // horizontal pair (j, j+1), weight 2; edges contribute p^2
        if (j < PW - 1) {
            const float d = p - sp[pix + 1];
            acc += 2.0f * d * d;
        } else {
            acc += p * p;                  // right edge
        }
        if (j == 0) acc += p * p;          // left edge

        // vertical pair (il, il+1): in-band always; band-crossing pair via
        // halo row (band<3). Last row of last band = bottom edge.
        if ((band < 3) || (il < BAND - 1)) {
            const float d = p - sp[pix + PW];
            acc += 2.0f * d * d;
        } else {
            acc += p * p;                  // bottom edge (global row 127)
        }
        if (band == 0 && il == 0) acc += p * p;   // top edge (global row 0)
    }

    // ---- block reduction (32 warps), one atomic per block (128 total)
#pragma unroll
    for (int off = 16; off > 0; off >>= 1)
        acc += __shfl_down_sync(0xFFFFFFFFu, acc, off);

    __shared__ float warp_sums[32];
    const int lane = threadIdx.x & 31;
    const int wid  = threadIdx.x >> 5;
    if (lane == 0) warp_sums[wid] = acc;
    __syncthreads();

    if (wid == 0) {
        float s = warp_sums[lane];
#pragma unroll
        for (int off = 16; off > 0; off >>= 1)
            s += __shfl_down_sync(0xFFFFFFFFu, s, off);
        if (lane == 0)
            atomicAdd(out, s * (1.0f / (float)NPIX));
    }
}

extern "C" void kernel_launch(void* const* d_in, const int* in_sizes, int n_in,
                              void* d_out, int out_size)
{
    const float* x    = (const float*)d_in[0];
    const float* pred = (const float*)d_in[1];
    float* out = (float*)d_out;

    cudaMemsetAsync(out, 0, sizeof(float));
    fused_spatial_loss_kernel<<<BB * 4, NTHR>>>(x, pred, out);  // 128 blocks
}